// round 3
// baseline (speedup 1.0000x reference)
#include <cuda_runtime.h>
#include <math.h>

#define BS 1024
#define SL 512
#define TT 64

// Per-batch partials (static device globals: no allocation). Every element is
// written on every launch -> deterministic.
__device__ float g_score[BS];
__device__ float g_logZ[BS];
__device__ int   g_count[BS];

// ---- packed f32x2 helpers (ptxas won't auto-fuse; PTX-only) ----------------
__device__ __forceinline__ unsigned long long ffma2(unsigned long long a,
                                                    unsigned long long b,
                                                    unsigned long long c) {
    unsigned long long d;
    asm("fma.rn.f32x2 %0, %1, %2, %3;" : "=l"(d) : "l"(a), "l"(b), "l"(c));
    return d;
}
__device__ __forceinline__ unsigned long long addf2(unsigned long long a,
                                                    unsigned long long b) {
    unsigned long long d;
    asm("add.rn.f32x2 %0, %1, %2;" : "=l"(d) : "l"(a), "l"(b));
    return d;
}
__device__ __forceinline__ unsigned long long pack2(float x, float y) {
    unsigned long long r;
    asm("mov.b64 %0, {%1, %2};" : "=l"(r) : "f"(x), "f"(y));
    return r;
}
__device__ __forceinline__ void unpack2(unsigned long long v, float& lo, float& hi) {
    asm("mov.b64 {%0, %1}, %2;" : "=f"(lo), "=f"(hi) : "l"(v));
}
__device__ __forceinline__ float rcp_approx(float x) {
    float r;
    asm("rcp.approx.f32 %0, %1;" : "=f"(r) : "f"(x));
    return r;
}

// ---------------------------------------------------------------------------
// Score kernel (unchanged): per-batch tag-path score + mask count.
// ---------------------------------------------------------------------------
__global__ void crf_score_kernel(const float* __restrict__ e,
                                 const int* __restrict__ tags,
                                 const unsigned char* __restrict__ mask,
                                 const float* __restrict__ st,
                                 const float* __restrict__ et,
                                 const float* __restrict__ t)
{
    const int b = blockIdx.x;
    const int tid = threadIdx.x;               // 128 threads
    const int* tg = tags + b * SL;
    const unsigned char* mk = mask + b * SL;
    const float* eb = e + (size_t)b * SL * TT;

    float s_local = 0.f;
    int c_local = 0;
    for (int s = tid; s < SL; s += 128) {
        int tag = tg[s];
        int m = mk[s] ? 1 : 0;
        if (s == 0) {
            s_local += st[tag] + eb[tag];
        } else if (m) {
            int tp = tg[s - 1];
            s_local += t[tp * TT + tag] + eb[(size_t)s * TT + tag];
        }
        c_local += m;
    }

    __shared__ float ssum[128];
    __shared__ int   scnt[128];
    ssum[tid] = s_local;
    scnt[tid] = c_local;
    __syncthreads();
    for (int off = 64; off > 0; off >>= 1) {
        if (tid < off) {
            ssum[tid] += ssum[tid + off];
            scnt[tid] += scnt[tid + off];
        }
        __syncthreads();
    }
    if (tid == 0) {
        float sc = ssum[0];
        int cnt = scnt[0];
        if (cnt > 0) sc += et[tg[cnt - 1]];
        g_score[b] = sc;
        g_count[b] = cnt;
    }
}

// ---------------------------------------------------------------------------
// Forward kernel: one block of 64 threads per batch; thread j owns state j.
// Alpha carried in LINEAR space, renormalized by a_prev[0] each step:
//   a_new[j] = (sum_i a[i]*P[i][j]) * exp(e[s][j]) * rcp(a_prev[0])
//   logb    += log2(a_prev[0])          (converted by ln2 at the end)
// Dot product uses packed fma.rn.f32x2 over a register-resident P column.
// ---------------------------------------------------------------------------
__global__ void __launch_bounds__(TT)
crf_forward_kernel(const float* __restrict__ e,
                   const unsigned char* __restrict__ mask,
                   const float* __restrict__ st,
                   const float* __restrict__ et,
                   const float* __restrict__ t)
{
    const int b = blockIdx.x;
    const int j = threadIdx.x;                 // state index

    __shared__ __align__(16) float a_sm[2][TT];
    __shared__ float wred[2];

    // Packed P column: Pp[q] = { exp(t[2q][j]), exp(t[2q+1][j]) }
    unsigned long long Pp[TT / 2];
#pragma unroll
    for (int q = 0; q < TT / 2; q++) {
        float p0 = __expf(t[(2 * q + 0) * TT + j]);
        float p1 = __expf(t[(2 * q + 1) * TT + j]);
        Pp[q] = pack2(p0, p1);
    }

    const float* eb = e + (size_t)b * SL * TT;
    const unsigned char* mk = mask + b * SL;

    float a = __expf(st[j] + eb[j]);           // linear alpha, step 0
    float logb = 0.f;                          // log2 of accumulated normalizer
    float E    = __expf(eb[TT + j]);           // exp(e[s=1][j])
    float eraw = eb[2 * TT + j];               // raw e[s=2][j] (prefetched)

    int par = 0;
    a_sm[0][j] = a;
    __syncthreads();

    for (int s = 1; s < SL; ++s) {
        // Prefetch e for s+2 (hides LDG behind the dot).
        int sn = (s + 2 < SL) ? (s + 2) : (SL - 1);
        float eraw2 = eb[(size_t)sn * TT + j];
        int m = mk[s] ? 1 : 0;                 // uniform across the block

        // Anchor terms: issue early, overlap with the dot (off critical path).
        float a0 = a_sm[par][0];
        float r  = rcp_approx(a0);
        float lg = __log2f(a0);

        const ulonglong2* av = (const ulonglong2*)(a_sm[par]);
        unsigned long long acc0 = 0ull, acc1 = 0ull, acc2 = 0ull, acc3 = 0ull;
#pragma unroll
        for (int q2 = 0; q2 < TT / 4; q2++) {
            ulonglong2 v = av[q2];             // LDS.128 broadcast: 4 floats = 2 f32x2
            if (q2 & 1) {
                acc2 = ffma2(v.x, Pp[2 * q2 + 0], acc2);
                acc3 = ffma2(v.y, Pp[2 * q2 + 1], acc3);
            } else {
                acc0 = ffma2(v.x, Pp[2 * q2 + 0], acc0);
                acc1 = ffma2(v.y, Pp[2 * q2 + 1], acc1);
            }
        }
        unsigned long long sp = addf2(addf2(acc0, acc2), addf2(acc1, acc3));
        float slo, shi;
        unpack2(sp, slo, shi);
        float sum = slo + shi;

        if (m) {
            a = sum * E * r;
            logb += lg;
        }
        E = __expf(eraw);                      // exp for step s+1 (off-path)
        eraw = eraw2;

        par ^= 1;
        a_sm[par][j] = a;
        __syncthreads();                       // one BAR per step
    }

    // logZ = ln2*logb + log( sum_j a[j] * exp(et[j]) )
    float f = a * __expf(et[j]);
    const int lane = j & 31;
    const int wid = j >> 5;
#pragma unroll
    for (int off = 16; off > 0; off >>= 1)
        f += __shfl_xor_sync(0xffffffffu, f, off);
    if (lane == 0) wred[wid] = f;
    __syncthreads();
    if (j == 0) {
        float total = wred[0] + wred[1];
        g_logZ[b] = 0.69314718055994531f * (logb + __log2f(total));
    }
}

// ---------------------------------------------------------------------------
// Deterministic final reduction: out = sum_b(score_b - logZ_b) / sum(mask)
// ---------------------------------------------------------------------------
__global__ void crf_finalize_kernel(float* __restrict__ out)
{
    const int tid = threadIdx.x;               // 256 threads
    float num = 0.f, tot = 0.f;
    for (int b = tid; b < BS; b += 256) {
        num += g_score[b] - g_logZ[b];
        tot += (float)g_count[b];
    }
    __shared__ float sn[256], stt[256];
    sn[tid] = num;
    stt[tid] = tot;
    __syncthreads();
    for (int off = 128; off > 0; off >>= 1) {
        if (tid < off) {
            sn[tid]  += sn[tid + off];
            stt[tid] += stt[tid + off];
        }
        __syncthreads();
    }
    if (tid == 0) out[0] = sn[0] / stt[0];
}

// ---------------------------------------------------------------------------
// Inputs (metadata order): e(f32), tags(i32), mask(bool->u8), st(f32),
// et(f32), t(f32). Output: single f32 scalar.
// ---------------------------------------------------------------------------
extern "C" void kernel_launch(void* const* d_in, const int* in_sizes, int n_in,
                              void* d_out, int out_size)
{
    const float*         e    = (const float*)d_in[0];
    const int*           tags = (const int*)d_in[1];
    const unsigned char* mask = (const unsigned char*)d_in[2];
    const float*         st   = (const float*)d_in[3];
    const float*         et   = (const float*)d_in[4];
    const float*         t    = (const float*)d_in[5];
    float* out = (float*)d_out;

    crf_score_kernel<<<BS, 128>>>(e, tags, mask, st, et, t);
    crf_forward_kernel<<<BS, TT>>>(e, mask, st, et, t);
    crf_finalize_kernel<<<1, 256>>>(out);
}